// round 8
// baseline (speedup 1.0000x reference)
#include <cuda_runtime.h>
#include <cuda_bf16.h>

// Problem constants (fixed by the reference setup)
constexpr int N_NODES = 50000;
constexpr int N_EDGES = 800000;
constexpr int NZ = N_NODES * 32;
constexpr int CAP = 96;   // bucket capacity; P(Poisson(16) > 89) ~ 1e-40

// Scratch (device globals; referenced ONLY from device code — host-side
// references to __device__ symbols pass the host shadow address on GB300/ATS).
// Feature tables have one extra zero row (node N_NODES) used as bucket padding,
// so pull loops need no remainder handling.
__device__ __align__(16) float g_dinv[N_NODES];
__device__ __align__(16) float g_ys32[(N_NODES + 1) * 32];   // dinv * x
__device__ __align__(16) float g_bufA[(N_NODES + 1) * 64];   // dinv * h1
__device__ __align__(16) float g_bufB[(N_NODES + 1) * 64];   // dinv * h2
__device__ int g_cnt[N_NODES];            // fill cursor, then padded count
__device__ int g_srcs[N_NODES * CAP];     // padded per-dst buckets
__device__ int g_is64;

// ---------------------------------------------------------------------------
__device__ __forceinline__ int edge_idx(const void* p, int pos, int is64) {
    if (is64) return (int)((const long long*)p)[pos];
    return ((const int*)p)[pos];
}

// Detect int64 vs int32 edge_index + zero cursors.
__global__ void detect_zero_kernel(const void* ei) {
    int i = blockIdx.x * blockDim.x + threadIdx.x;
    if (i < N_NODES) g_cnt[i] = 0;
    if (i == 0) {
        const long long* p = (const long long*)ei;
        int ok = 1;
        for (int k = 0; k < 256; k++) {
            long long v = p[k];
            if (v < 0 || v >= N_NODES) { ok = 0; break; }
        }
        g_is64 = ok;
    }
}

// Direct bucket fill: srcs[d*CAP + cursor++] = s.  4 edges/thread for ILP.
__global__ void fill_kernel(const void* ei) {
    int is64 = g_is64;
    int base = (blockIdx.x * blockDim.x + threadIdx.x) * 4;
    if (base + 4 <= N_EDGES) {
        int s0, s1, s2, s3, d0, d1, d2, d3;
        if (!is64) {
            int4 sv = *(const int4*)((const int*)ei + base);
            int4 dv = *(const int4*)((const int*)ei + N_EDGES + base);
            s0 = sv.x; s1 = sv.y; s2 = sv.z; s3 = sv.w;
            d0 = dv.x; d1 = dv.y; d2 = dv.z; d3 = dv.w;
        } else {
            const long long* ps = (const long long*)ei + base;
            const long long* pd = (const long long*)ei + N_EDGES + base;
            s0 = (int)ps[0]; s1 = (int)ps[1]; s2 = (int)ps[2]; s3 = (int)ps[3];
            d0 = (int)pd[0]; d1 = (int)pd[1]; d2 = (int)pd[2]; d3 = (int)pd[3];
        }
        int p0 = atomicAdd(&g_cnt[d0], 1);
        int p1 = atomicAdd(&g_cnt[d1], 1);
        int p2 = atomicAdd(&g_cnt[d2], 1);
        int p3 = atomicAdd(&g_cnt[d3], 1);
        g_srcs[d0 * CAP + p0] = s0;
        g_srcs[d1 * CAP + p1] = s1;
        g_srcs[d2 * CAP + p2] = s2;
        g_srcs[d3 * CAP + p3] = s3;
    } else {
        for (int e = base; e < N_EDGES; e++) {
            int s = edge_idx(ei, e, is64);
            int d = edge_idx(ei, N_EDGES + e, is64);
            int pos = atomicAdd(&g_cnt[d], 1);
            g_srcs[d * CAP + pos] = s;
        }
    }
}

// Per node: dinv from count, pad bucket to multiple of 8 with node N_NODES,
// store padded count, scale ys32 = dinv*x. Thread N_NODES zeroes spare rows.
__global__ void prep_kernel(const float* __restrict__ x) {
    int n = blockIdx.x * blockDim.x + threadIdx.x;
    if (n < N_NODES) {
        int c = g_cnt[n];
        int r8 = (c + 7) & ~7;
        for (int k = c; k < r8; k++) g_srcs[n * CAP + k] = N_NODES;
        g_cnt[n] = r8;
        float dv = rsqrtf((float)(c + 1));   // deg incl. self-loop
        g_dinv[n] = dv;
        const float4* x4 = (const float4*)x;
        float4* y4 = (float4*)g_ys32;
#pragma unroll
        for (int k = 0; k < 8; k++) {
            float4 v = x4[n * 8 + k];
            y4[n * 8 + k] = make_float4(dv * v.x, dv * v.y, dv * v.z, dv * v.w);
        }
    } else if (n == N_NODES) {
        // zero the padding rows (persist across the kernel sequence)
        float4* y4 = (float4*)g_ys32;
        float4* a4 = (float4*)g_bufA;
        float4* b4 = (float4*)g_bufB;
        float4 z = make_float4(0.f, 0.f, 0.f, 0.f);
#pragma unroll
        for (int k = 0; k < 8; k++) y4[N_NODES * 8 + k] = z;
#pragma unroll
        for (int k = 0; k < 16; k++) {
            a4[N_NODES * 16 + k] = z;
            b4[N_NODES * 16 + k] = z;
        }
    }
}

// ---------------------------------------------------------------------------
// Fused pull + GEMM kernels. 256 threads = 8 warps; one warp per node.
// Buckets padded to multiple of 8 -> gather loops are branch-free.
//   pull1: quarter-warp per 32-dim row, x2 unroll (8 gathers in flight)
//   pull2/3: half-warp per 64-dim row, x2 unroll (4 gathers in flight)
// ---------------------------------------------------------------------------

// Layer 1: a[32] = dinv*(Σ ys32[src] + ys32[n]); bufA = dinv*relu(a@W1 + b1)
__global__ void __launch_bounds__(256) pull1_kernel(
    const float* __restrict__ W1, const float* __restrict__ b1) {
    __shared__ float sW[32 * 64];
    __shared__ float sb[64];
    __shared__ float4 sa[8][8];   // 8 warps x 32 floats
    int tid = threadIdx.x;
    for (int i = tid; i < 32 * 64; i += 256) sW[i] = W1[i];
    if (tid < 64) sb[tid] = b1[tid];
    __syncthreads();

    int w = tid >> 5, lane = tid & 31;
    int grp = lane >> 3;      // 0..3 — row within gather group
    int sub = lane & 7;       // float4 slot within the 32-dim row
    const float4* ys4 = (const float4*)g_ys32;
    for (int n = blockIdx.x * 8 + w; n < N_NODES; n += gridDim.x * 8) {
        int base = n * CAP, m = g_cnt[n];   // padded to multiple of 8
        float4 acc0 = (grp == 0) ? ys4[n * 8 + sub] : make_float4(0.f, 0.f, 0.f, 0.f);
        float4 acc1 = make_float4(0.f, 0.f, 0.f, 0.f);
        for (int e = 0; e < m; e += 8) {
            int s0 = g_srcs[base + e + grp];
            int s1 = g_srcs[base + e + 4 + grp];
            float4 v0 = ys4[s0 * 8 + sub];
            float4 v1 = ys4[s1 * 8 + sub];
            acc0.x += v0.x; acc0.y += v0.y; acc0.z += v0.z; acc0.w += v0.w;
            acc1.x += v1.x; acc1.y += v1.y; acc1.z += v1.z; acc1.w += v1.w;
        }
        float4 a = make_float4(acc0.x + acc1.x, acc0.y + acc1.y,
                               acc0.z + acc1.z, acc0.w + acc1.w);
        a.x += __shfl_xor_sync(0xffffffffu, a.x, 8);
        a.y += __shfl_xor_sync(0xffffffffu, a.y, 8);
        a.z += __shfl_xor_sync(0xffffffffu, a.z, 8);
        a.w += __shfl_xor_sync(0xffffffffu, a.w, 8);
        a.x += __shfl_xor_sync(0xffffffffu, a.x, 16);
        a.y += __shfl_xor_sync(0xffffffffu, a.y, 16);
        a.z += __shfl_xor_sync(0xffffffffu, a.z, 16);
        a.w += __shfl_xor_sync(0xffffffffu, a.w, 16);
        float dv = g_dinv[n];
        if (grp == 0)
            sa[w][sub] = make_float4(dv * a.x, dv * a.y, dv * a.z, dv * a.w);
        __syncwarp();
        // GEMM: this lane computes outputs 2*lane, 2*lane+1
        float s0 = sb[2 * lane], s1 = sb[2 * lane + 1];
#pragma unroll
        for (int k4 = 0; k4 < 8; k4++) {
            float4 aa = sa[w][k4];
            float2 r0 = *(const float2*)&sW[(4 * k4 + 0) * 64 + 2 * lane];
            float2 r1 = *(const float2*)&sW[(4 * k4 + 1) * 64 + 2 * lane];
            float2 r2 = *(const float2*)&sW[(4 * k4 + 2) * 64 + 2 * lane];
            float2 r3 = *(const float2*)&sW[(4 * k4 + 3) * 64 + 2 * lane];
            s0 = fmaf(aa.x, r0.x, s0); s1 = fmaf(aa.x, r0.y, s1);
            s0 = fmaf(aa.y, r1.x, s0); s1 = fmaf(aa.y, r1.y, s1);
            s0 = fmaf(aa.z, r2.x, s0); s1 = fmaf(aa.z, r2.y, s1);
            s0 = fmaf(aa.w, r3.x, s0); s1 = fmaf(aa.w, r3.y, s1);
        }
        float2 o = make_float2(dv * fmaxf(s0, 0.f), dv * fmaxf(s1, 0.f));
        ((float2*)g_bufA)[n * 32 + lane] = o;
        __syncwarp();   // everyone done with sa[w] before next iteration
    }
}

// 64-dim pull: half-warp per row, float4 lanes, x2 unroll, branch-free.
__device__ __forceinline__ float4 pull64v(const float4* __restrict__ in4,
                                          int n, int half, int sub) {
    int base = n * CAP, m = g_cnt[n];
    float4 acc0 = (half == 0) ? in4[n * 16 + sub] : make_float4(0.f, 0.f, 0.f, 0.f);
    float4 acc1 = make_float4(0.f, 0.f, 0.f, 0.f);
    for (int e = 0; e < m; e += 4) {
        int s0 = g_srcs[base + e + half];
        int s1 = g_srcs[base + e + 2 + half];
        float4 v0 = in4[s0 * 16 + sub];
        float4 v1 = in4[s1 * 16 + sub];
        acc0.x += v0.x; acc0.y += v0.y; acc0.z += v0.z; acc0.w += v0.w;
        acc1.x += v1.x; acc1.y += v1.y; acc1.z += v1.z; acc1.w += v1.w;
    }
    float4 a = make_float4(acc0.x + acc1.x, acc0.y + acc1.y,
                           acc0.z + acc1.z, acc0.w + acc1.w);
    a.x += __shfl_xor_sync(0xffffffffu, a.x, 16);
    a.y += __shfl_xor_sync(0xffffffffu, a.y, 16);
    a.z += __shfl_xor_sync(0xffffffffu, a.z, 16);
    a.w += __shfl_xor_sync(0xffffffffu, a.w, 16);
    return a;
}

// Layer 2: pull 64-dim from bufA, GEMM 64x64, bufB = dinv*relu(.)
__global__ void __launch_bounds__(256) pull2_kernel(
    const float* __restrict__ W2, const float* __restrict__ b2) {
    __shared__ float sW[64 * 64];
    __shared__ float sb[64];
    __shared__ float4 sa[8][16];  // 8 warps x 64 floats
    int tid = threadIdx.x;
    for (int i = tid; i < 64 * 64; i += 256) sW[i] = W2[i];
    if (tid < 64) sb[tid] = b2[tid];
    __syncthreads();

    int w = tid >> 5, lane = tid & 31;
    int half = lane >> 4, sub = lane & 15;
    const float4* in4 = (const float4*)g_bufA;
    for (int n = blockIdx.x * 8 + w; n < N_NODES; n += gridDim.x * 8) {
        float4 a = pull64v(in4, n, half, sub);
        float dv = g_dinv[n];
        if (half == 0)
            sa[w][sub] = make_float4(dv * a.x, dv * a.y, dv * a.z, dv * a.w);
        __syncwarp();
        float s0 = sb[2 * lane], s1 = sb[2 * lane + 1];
#pragma unroll
        for (int k4 = 0; k4 < 16; k4++) {
            float4 aa = sa[w][k4];
            float2 r0 = *(const float2*)&sW[(4 * k4 + 0) * 64 + 2 * lane];
            float2 r1 = *(const float2*)&sW[(4 * k4 + 1) * 64 + 2 * lane];
            float2 r2 = *(const float2*)&sW[(4 * k4 + 2) * 64 + 2 * lane];
            float2 r3 = *(const float2*)&sW[(4 * k4 + 3) * 64 + 2 * lane];
            s0 = fmaf(aa.x, r0.x, s0); s1 = fmaf(aa.x, r0.y, s1);
            s0 = fmaf(aa.y, r1.x, s0); s1 = fmaf(aa.y, r1.y, s1);
            s0 = fmaf(aa.z, r2.x, s0); s1 = fmaf(aa.z, r2.y, s1);
            s0 = fmaf(aa.w, r3.x, s0); s1 = fmaf(aa.w, r3.y, s1);
        }
        float2 o = make_float2(dv * fmaxf(s0, 0.f), dv * fmaxf(s1, 0.f));
        ((float2*)g_bufB)[n * 32 + lane] = o;
        __syncwarp();
    }
}

// Heads: pull 64-dim from bufB (ONE aggregation for both heads),
// mu = a@W_mu+b_mu, lv = a@W_lv+b_lv, z = mu + exp(0.5 lv)*eps.
// Output layout: [z | mu | logvar].
__global__ void __launch_bounds__(256) pull3_kernel(
    const float* __restrict__ W_mu, const float* __restrict__ b_mu,
    const float* __restrict__ W_lv, const float* __restrict__ b_lv,
    const float* __restrict__ eps, float* __restrict__ out) {
    __shared__ float2 sWml[64 * 32];   // interleaved {Wmu, Wlv}
    __shared__ float sbm[32], sbl[32];
    __shared__ float4 sa[8][16];
    int tid = threadIdx.x;
    for (int i = tid; i < 64 * 32; i += 256)
        sWml[i] = make_float2(W_mu[i], W_lv[i]);
    if (tid < 32) { sbm[tid] = b_mu[tid]; sbl[tid] = b_lv[tid]; }
    __syncthreads();

    int w = tid >> 5, lane = tid & 31;
    int half = lane >> 4, sub = lane & 15;
    const float4* in4 = (const float4*)g_bufB;
    for (int n = blockIdx.x * 8 + w; n < N_NODES; n += gridDim.x * 8) {
        float4 a = pull64v(in4, n, half, sub);
        float dv = g_dinv[n];
        if (half == 0)
            sa[w][sub] = make_float4(dv * a.x, dv * a.y, dv * a.z, dv * a.w);
        __syncwarp();
        float mu = sbm[lane], lv = sbl[lane];
#pragma unroll
        for (int k4 = 0; k4 < 16; k4++) {
            float4 aa = sa[w][k4];
            float2 m0 = sWml[(4 * k4 + 0) * 32 + lane];
            float2 m1 = sWml[(4 * k4 + 1) * 32 + lane];
            float2 m2 = sWml[(4 * k4 + 2) * 32 + lane];
            float2 m3 = sWml[(4 * k4 + 3) * 32 + lane];
            mu = fmaf(aa.x, m0.x, mu); lv = fmaf(aa.x, m0.y, lv);
            mu = fmaf(aa.y, m1.x, mu); lv = fmaf(aa.y, m1.y, lv);
            mu = fmaf(aa.z, m2.x, mu); lv = fmaf(aa.z, m2.y, lv);
            mu = fmaf(aa.w, m3.x, mu); lv = fmaf(aa.w, m3.y, lv);
        }
        float z = fmaf(expf(0.5f * lv), eps[n * 32 + lane], mu);
        int o = n * 32 + lane;
        out[o] = z;
        out[NZ + o] = mu;
        out[2 * NZ + o] = lv;
        __syncwarp();
    }
}

// ---------------------------------------------------------------------------
extern "C" void kernel_launch(void* const* d_in, const int* in_sizes, int n_in,
                              void* d_out, int out_size) {
    const float* x    = (const float*)d_in[0];
    const void*  ei   = d_in[1];
    const float* W1   = (const float*)d_in[2];
    const float* b1   = (const float*)d_in[3];
    const float* W2   = (const float*)d_in[4];
    const float* b2   = (const float*)d_in[5];
    const float* W_mu = (const float*)d_in[6];
    const float* b_mu = (const float*)d_in[7];
    const float* W_lv = (const float*)d_in[8];
    const float* b_lv = (const float*)d_in[9];
    const float* eps  = (const float*)d_in[10];
    float* out = (float*)d_out;

    const int TB = 256;
    auto grid = [](long long n, int tb) { return (int)((n + tb - 1) / tb); };
    const int PG = 1184;   // persistent pull blocks

    detect_zero_kernel<<<grid(N_NODES, TB), TB>>>(ei);
    fill_kernel<<<grid((N_EDGES + 3) / 4, TB), TB>>>(ei);
    prep_kernel<<<grid(N_NODES + 1, TB), TB>>>(x);

    pull1_kernel<<<PG, 256>>>(W1, b1);
    pull2_kernel<<<PG, 256>>>(W2, b2);
    pull3_kernel<<<PG, 256>>>(W_mu, b_mu, W_lv, b_lv, eps, out);
}

// round 9
// speedup vs baseline: 1.1584x; 1.1584x over previous
#include <cuda_runtime.h>
#include <cuda_bf16.h>

// Problem constants (fixed by the reference setup)
constexpr int N_NODES = 50000;
constexpr int N_EDGES = 800000;
constexpr int NZ = N_NODES * 32;
constexpr int CAP = 96;        // bucket capacity; P(Poisson(16) > 89) ~ 1e-40
constexpr int NGROUPS = N_NODES / 8;   // 6250 (50000 divisible by 8)
constexpr int PB = (NGROUPS + 7) / 8;  // 782 blocks, 8 warps = 8 groups each

// Scratch (device globals; referenced ONLY from device code — host-side
// references to __device__ symbols pass the host shadow address on GB300/ATS).
// Feature tables have one extra zero row (node N_NODES) used as bucket padding.
__device__ __align__(16) float g_dinv[N_NODES];
__device__ __align__(16) float g_ys32[(N_NODES + 1) * 32];   // dinv * x
__device__ __align__(16) float g_bufA[(N_NODES + 1) * 64];   // dinv * h1
__device__ __align__(16) float g_bufB[(N_NODES + 1) * 64];   // dinv * h2
__device__ int g_cnt[N_NODES];            // fill cursor, then padded count
__device__ int g_srcs[N_NODES * CAP];     // padded per-dst buckets
__device__ int g_is64;

// ---------------------------------------------------------------------------
__device__ __forceinline__ int edge_idx(const void* p, int pos, int is64) {
    if (is64) return (int)((const long long*)p)[pos];
    return ((const int*)p)[pos];
}

// Detect int64 vs int32 edge_index + zero cursors.
__global__ void detect_zero_kernel(const void* ei) {
    int i = blockIdx.x * blockDim.x + threadIdx.x;
    if (i < N_NODES) g_cnt[i] = 0;
    if (i == 0) {
        const long long* p = (const long long*)ei;
        int ok = 1;
        for (int k = 0; k < 256; k++) {
            long long v = p[k];
            if (v < 0 || v >= N_NODES) { ok = 0; break; }
        }
        g_is64 = ok;
    }
}

// Direct bucket fill: srcs[d*CAP + cursor++] = s.  4 edges/thread.
__global__ void fill_kernel(const void* ei) {
    int is64 = g_is64;
    int base = (blockIdx.x * blockDim.x + threadIdx.x) * 4;
    if (base + 4 <= N_EDGES) {
        int s0, s1, s2, s3, d0, d1, d2, d3;
        if (!is64) {
            int4 sv = *(const int4*)((const int*)ei + base);
            int4 dv = *(const int4*)((const int*)ei + N_EDGES + base);
            s0 = sv.x; s1 = sv.y; s2 = sv.z; s3 = sv.w;
            d0 = dv.x; d1 = dv.y; d2 = dv.z; d3 = dv.w;
        } else {
            const long long* ps = (const long long*)ei + base;
            const long long* pd = (const long long*)ei + N_EDGES + base;
            s0 = (int)ps[0]; s1 = (int)ps[1]; s2 = (int)ps[2]; s3 = (int)ps[3];
            d0 = (int)pd[0]; d1 = (int)pd[1]; d2 = (int)pd[2]; d3 = (int)pd[3];
        }
        int p0 = atomicAdd(&g_cnt[d0], 1);
        int p1 = atomicAdd(&g_cnt[d1], 1);
        int p2 = atomicAdd(&g_cnt[d2], 1);
        int p3 = atomicAdd(&g_cnt[d3], 1);
        g_srcs[d0 * CAP + p0] = s0;
        g_srcs[d1 * CAP + p1] = s1;
        g_srcs[d2 * CAP + p2] = s2;
        g_srcs[d3 * CAP + p3] = s3;
    } else {
        for (int e = base; e < N_EDGES; e++) {
            int s = edge_idx(ei, e, is64);
            int d = edge_idx(ei, N_EDGES + e, is64);
            int pos = atomicAdd(&g_cnt[d], 1);
            g_srcs[d * CAP + pos] = s;
        }
    }
}

// Per node: dinv from count, pad bucket to multiple of 8 with node N_NODES,
// store padded count, scale ys32 = dinv*x. Thread N_NODES zeroes dummy rows.
__global__ void prep_kernel(const float* __restrict__ x) {
    int n = blockIdx.x * blockDim.x + threadIdx.x;
    if (n < N_NODES) {
        int c = g_cnt[n];
        int r8 = (c + 7) & ~7;
        for (int k = c; k < r8; k++) g_srcs[n * CAP + k] = N_NODES;
        g_cnt[n] = r8;
        float dv = rsqrtf((float)(c + 1));   // deg incl. self-loop
        g_dinv[n] = dv;
        const float4* x4 = (const float4*)x;
        float4* y4 = (float4*)g_ys32;
#pragma unroll
        for (int k = 0; k < 8; k++) {
            float4 v = x4[n * 8 + k];
            y4[n * 8 + k] = make_float4(dv * v.x, dv * v.y, dv * v.z, dv * v.w);
        }
    } else if (n == N_NODES) {
        float4* y4 = (float4*)g_ys32;
        float4* a4 = (float4*)g_bufA;
        float4* b4 = (float4*)g_bufB;
        float4 z = make_float4(0.f, 0.f, 0.f, 0.f);
#pragma unroll
        for (int k = 0; k < 8; k++) y4[N_NODES * 8 + k] = z;
#pragma unroll
        for (int k = 0; k < 16; k++) {
            a4[N_NODES * 16 + k] = z;
            b4[N_NODES * 16 + k] = z;
        }
    }
}

// ---------------------------------------------------------------------------
// Pull kernels, 8-node-batched GEMM.
// Each warp owns 8 consecutive nodes: Phase A aggregates them into shared
// (scaled by dinv), Phase B runs one register-accumulated GEMM for all 8,
// amortizing weight LDS 8x. Weights stored transposed with row stride
// = dim + 4 words (≡ 4 mod 32) -> conflict-free LDS.128.
// ---------------------------------------------------------------------------

// Layer 1: in 32 (g_ys32), out 64 -> bufA = dinv*relu(a@W1+b1)
__global__ void __launch_bounds__(256) pull1_kernel(
    const float* __restrict__ W1, const float* __restrict__ b1) {
    __shared__ float sWT[64 * 36];      // [j=64][k=32], stride 36
    __shared__ float sb[64];
    __shared__ float sa[8][8 * 36];     // [warp][node g][32 floats, stride 36]
    __shared__ float sdv[8][8];
    int tid = threadIdx.x;
    for (int i = tid; i < 2048; i += 256) {
        int k = i >> 6, j = i & 63;
        sWT[j * 36 + k] = W1[i];
    }
    if (tid < 64) sb[tid] = b1[tid];
    __syncthreads();

    int w = tid >> 5, lane = tid & 31;
    int grp = lane >> 3, sub = lane & 7;
    int G = blockIdx.x * 8 + w;
    if (G >= NGROUPS) return;
    int n0 = G * 8;
    const float4* ys4 = (const float4*)g_ys32;

    // Phase A: aggregate 8 nodes
    for (int g = 0; g < 8; g++) {
        int n = n0 + g;
        int base = n * CAP, m = g_cnt[n];
        float4 acc0 = (grp == 0) ? ys4[n * 8 + sub] : make_float4(0.f, 0.f, 0.f, 0.f);
        float4 acc1 = make_float4(0.f, 0.f, 0.f, 0.f);
        for (int e = 0; e < m; e += 8) {
            int s0 = g_srcs[base + e + grp];
            int s1 = g_srcs[base + e + 4 + grp];
            float4 v0 = ys4[s0 * 8 + sub];
            float4 v1 = ys4[s1 * 8 + sub];
            acc0.x += v0.x; acc0.y += v0.y; acc0.z += v0.z; acc0.w += v0.w;
            acc1.x += v1.x; acc1.y += v1.y; acc1.z += v1.z; acc1.w += v1.w;
        }
        float4 a = make_float4(acc0.x + acc1.x, acc0.y + acc1.y,
                               acc0.z + acc1.z, acc0.w + acc1.w);
        a.x += __shfl_xor_sync(0xffffffffu, a.x, 8);
        a.y += __shfl_xor_sync(0xffffffffu, a.y, 8);
        a.z += __shfl_xor_sync(0xffffffffu, a.z, 8);
        a.w += __shfl_xor_sync(0xffffffffu, a.w, 8);
        a.x += __shfl_xor_sync(0xffffffffu, a.x, 16);
        a.y += __shfl_xor_sync(0xffffffffu, a.y, 16);
        a.z += __shfl_xor_sync(0xffffffffu, a.z, 16);
        a.w += __shfl_xor_sync(0xffffffffu, a.w, 16);
        float dv = g_dinv[n];
        if (lane == 0) sdv[w][g] = dv;
        if (grp == 0)
            *(float4*)&sa[w][g * 36 + 4 * sub] =
                make_float4(dv * a.x, dv * a.y, dv * a.z, dv * a.w);
    }
    __syncwarp();

    // Phase B: GEMM for 8 nodes; lane -> output cols (lane, lane+32)
    float bj0 = sb[lane], bj1 = sb[lane + 32];
    float s0[8], s1[8];
#pragma unroll
    for (int g = 0; g < 8; g++) { s0[g] = bj0; s1[g] = bj1; }
#pragma unroll
    for (int k4 = 0; k4 < 8; k4++) {
        float4 w0 = *(const float4*)&sWT[lane * 36 + 4 * k4];
        float4 w1 = *(const float4*)&sWT[(lane + 32) * 36 + 4 * k4];
#pragma unroll
        for (int g = 0; g < 8; g++) {
            float4 a = *(const float4*)&sa[w][g * 36 + 4 * k4];
            s0[g] = fmaf(a.x, w0.x, s0[g]); s1[g] = fmaf(a.x, w1.x, s1[g]);
            s0[g] = fmaf(a.y, w0.y, s0[g]); s1[g] = fmaf(a.y, w1.y, s1[g]);
            s0[g] = fmaf(a.z, w0.z, s0[g]); s1[g] = fmaf(a.z, w1.z, s1[g]);
            s0[g] = fmaf(a.w, w0.w, s0[g]); s1[g] = fmaf(a.w, w1.w, s1[g]);
        }
    }
#pragma unroll
    for (int g = 0; g < 8; g++) {
        int n = n0 + g;
        float dv = sdv[w][g];
        g_bufA[n * 64 + lane]      = dv * fmaxf(s0[g], 0.f);
        g_bufA[n * 64 + lane + 32] = dv * fmaxf(s1[g], 0.f);
    }
}

// Layer 2: in 64 (bufA), out 64 -> bufB = dinv*relu(a@W2+b2)
__global__ void __launch_bounds__(256) pull2_kernel(
    const float* __restrict__ W2, const float* __restrict__ b2) {
    __shared__ float sWT[64 * 68];      // [j=64][k=64], stride 68
    __shared__ float sb[64];
    __shared__ float sa[8][8 * 68];
    __shared__ float sdv[8][8];
    int tid = threadIdx.x;
    for (int i = tid; i < 4096; i += 256) {
        int k = i >> 6, j = i & 63;
        sWT[j * 68 + k] = W2[i];
    }
    if (tid < 64) sb[tid] = b2[tid];
    __syncthreads();

    int w = tid >> 5, lane = tid & 31;
    int half = lane >> 4, sub = lane & 15;
    int G = blockIdx.x * 8 + w;
    if (G >= NGROUPS) return;
    int n0 = G * 8;
    const float4* in4 = (const float4*)g_bufA;

    for (int g = 0; g < 8; g++) {
        int n = n0 + g;
        int base = n * CAP, m = g_cnt[n];
        float4 acc0 = (half == 0) ? in4[n * 16 + sub] : make_float4(0.f, 0.f, 0.f, 0.f);
        float4 acc1 = make_float4(0.f, 0.f, 0.f, 0.f);
        for (int e = 0; e < m; e += 4) {
            int s0 = g_srcs[base + e + half];
            int s1 = g_srcs[base + e + 2 + half];
            float4 v0 = in4[s0 * 16 + sub];
            float4 v1 = in4[s1 * 16 + sub];
            acc0.x += v0.x; acc0.y += v0.y; acc0.z += v0.z; acc0.w += v0.w;
            acc1.x += v1.x; acc1.y += v1.y; acc1.z += v1.z; acc1.w += v1.w;
        }
        float4 a = make_float4(acc0.x + acc1.x, acc0.y + acc1.y,
                               acc0.z + acc1.z, acc0.w + acc1.w);
        a.x += __shfl_xor_sync(0xffffffffu, a.x, 16);
        a.y += __shfl_xor_sync(0xffffffffu, a.y, 16);
        a.z += __shfl_xor_sync(0xffffffffu, a.z, 16);
        a.w += __shfl_xor_sync(0xffffffffu, a.w, 16);
        float dv = g_dinv[n];
        if (lane == 0) sdv[w][g] = dv;
        if (half == 0)
            *(float4*)&sa[w][g * 68 + 4 * sub] =
                make_float4(dv * a.x, dv * a.y, dv * a.z, dv * a.w);
    }
    __syncwarp();

    float bj0 = sb[lane], bj1 = sb[lane + 32];
    float s0[8], s1[8];
#pragma unroll
    for (int g = 0; g < 8; g++) { s0[g] = bj0; s1[g] = bj1; }
#pragma unroll
    for (int k4 = 0; k4 < 16; k4++) {
        float4 w0 = *(const float4*)&sWT[lane * 68 + 4 * k4];
        float4 w1 = *(const float4*)&sWT[(lane + 32) * 68 + 4 * k4];
#pragma unroll
        for (int g = 0; g < 8; g++) {
            float4 a = *(const float4*)&sa[w][g * 68 + 4 * k4];
            s0[g] = fmaf(a.x, w0.x, s0[g]); s1[g] = fmaf(a.x, w1.x, s1[g]);
            s0[g] = fmaf(a.y, w0.y, s0[g]); s1[g] = fmaf(a.y, w1.y, s1[g]);
            s0[g] = fmaf(a.z, w0.z, s0[g]); s1[g] = fmaf(a.z, w1.z, s1[g]);
            s0[g] = fmaf(a.w, w0.w, s0[g]); s1[g] = fmaf(a.w, w1.w, s1[g]);
        }
    }
#pragma unroll
    for (int g = 0; g < 8; g++) {
        int n = n0 + g;
        float dv = sdv[w][g];
        g_bufB[n * 64 + lane]      = dv * fmaxf(s0[g], 0.f);
        g_bufB[n * 64 + lane + 32] = dv * fmaxf(s1[g], 0.f);
    }
}

// Heads: in 64 (bufB); mu = a@W_mu+b_mu, lv = a@W_lv+b_lv,
// z = mu + exp(0.5 lv)*eps.  Output layout: [z | mu | logvar].
__global__ void __launch_bounds__(256) pull3_kernel(
    const float* __restrict__ W_mu, const float* __restrict__ b_mu,
    const float* __restrict__ W_lv, const float* __restrict__ b_lv,
    const float* __restrict__ eps, float* __restrict__ out) {
    __shared__ float sWm[32 * 68];      // [j=32][k=64], stride 68
    __shared__ float sWl[32 * 68];
    __shared__ float sbm[32], sbl[32];
    __shared__ float sa[8][8 * 68];
    __shared__ float sdv[8][8];
    int tid = threadIdx.x;
    for (int i = tid; i < 2048; i += 256) {
        int k = i >> 5, j = i & 31;
        sWm[j * 68 + k] = W_mu[i];
        sWl[j * 68 + k] = W_lv[i];
    }
    if (tid < 32) { sbm[tid] = b_mu[tid]; sbl[tid] = b_lv[tid]; }
    __syncthreads();

    int w = tid >> 5, lane = tid & 31;
    int half = lane >> 4, sub = lane & 15;
    int G = blockIdx.x * 8 + w;
    if (G >= NGROUPS) return;
    int n0 = G * 8;
    const float4* in4 = (const float4*)g_bufB;

    for (int g = 0; g < 8; g++) {
        int n = n0 + g;
        int base = n * CAP, m = g_cnt[n];
        float4 acc0 = (half == 0) ? in4[n * 16 + sub] : make_float4(0.f, 0.f, 0.f, 0.f);
        float4 acc1 = make_float4(0.f, 0.f, 0.f, 0.f);
        for (int e = 0; e < m; e += 4) {
            int s0 = g_srcs[base + e + half];
            int s1 = g_srcs[base + e + 2 + half];
            float4 v0 = in4[s0 * 16 + sub];
            float4 v1 = in4[s1 * 16 + sub];
            acc0.x += v0.x; acc0.y += v0.y; acc0.z += v0.z; acc0.w += v0.w;
            acc1.x += v1.x; acc1.y += v1.y; acc1.z += v1.z; acc1.w += v1.w;
        }
        float4 a = make_float4(acc0.x + acc1.x, acc0.y + acc1.y,
                               acc0.z + acc1.z, acc0.w + acc1.w);
        a.x += __shfl_xor_sync(0xffffffffu, a.x, 16);
        a.y += __shfl_xor_sync(0xffffffffu, a.y, 16);
        a.z += __shfl_xor_sync(0xffffffffu, a.z, 16);
        a.w += __shfl_xor_sync(0xffffffffu, a.w, 16);
        float dv = g_dinv[n];
        if (lane == 0) sdv[w][g] = dv;
        if (half == 0)
            *(float4*)&sa[w][g * 68 + 4 * sub] =
                make_float4(dv * a.x, dv * a.y, dv * a.z, dv * a.w);
    }
    __syncwarp();

    float bm = sbm[lane], bl = sbl[lane];
    float smu[8], slv[8];
#pragma unroll
    for (int g = 0; g < 8; g++) { smu[g] = bm; slv[g] = bl; }
#pragma unroll
    for (int k4 = 0; k4 < 16; k4++) {
        float4 wm = *(const float4*)&sWm[lane * 68 + 4 * k4];
        float4 wl = *(const float4*)&sWl[lane * 68 + 4 * k4];
#pragma unroll
        for (int g = 0; g < 8; g++) {
            float4 a = *(const float4*)&sa[w][g * 68 + 4 * k4];
            smu[g] = fmaf(a.x, wm.x, smu[g]); slv[g] = fmaf(a.x, wl.x, slv[g]);
            smu[g] = fmaf(a.y, wm.y, smu[g]); slv[g] = fmaf(a.y, wl.y, slv[g]);
            smu[g] = fmaf(a.z, wm.z, smu[g]); slv[g] = fmaf(a.z, wl.z, slv[g]);
            smu[g] = fmaf(a.w, wm.w, smu[g]); slv[g] = fmaf(a.w, wl.w, slv[g]);
        }
    }
#pragma unroll
    for (int g = 0; g < 8; g++) {
        int n = n0 + g;
        float mu = smu[g], lv = slv[g];
        float z = fmaf(expf(0.5f * lv), eps[n * 32 + lane], mu);
        int o = n * 32 + lane;
        out[o] = z;
        out[NZ + o] = mu;
        out[2 * NZ + o] = lv;
    }
}

// ---------------------------------------------------------------------------
extern "C" void kernel_launch(void* const* d_in, const int* in_sizes, int n_in,
                              void* d_out, int out_size) {
    const float* x    = (const float*)d_in[0];
    const void*  ei   = d_in[1];
    const float* W1   = (const float*)d_in[2];
    const float* b1   = (const float*)d_in[3];
    const float* W2   = (const float*)d_in[4];
    const float* b2   = (const float*)d_in[5];
    const float* W_mu = (const float*)d_in[6];
    const float* b_mu = (const float*)d_in[7];
    const float* W_lv = (const float*)d_in[8];
    const float* b_lv = (const float*)d_in[9];
    const float* eps  = (const float*)d_in[10];
    float* out = (float*)d_out;

    const int TB = 256;
    auto grid = [](long long n, int tb) { return (int)((n + tb - 1) / tb); };

    detect_zero_kernel<<<grid(N_NODES, TB), TB>>>(ei);
    fill_kernel<<<grid((N_EDGES + 3) / 4, TB), TB>>>(ei);
    prep_kernel<<<grid(N_NODES + 1, TB), TB>>>(x);

    pull1_kernel<<<PB, 256>>>(W1, b1);
    pull2_kernel<<<PB, 256>>>(W2, b2);
    pull3_kernel<<<PB, 256>>>(W_mu, b_mu, W_lv, b_lv, eps, out);
}